// round 11
// baseline (speedup 1.0000x reference)
#include <cuda_runtime.h>
#include <cuda_fp16.h>
#include <cstdint>

// FlashAttention B=2,H=16,S=4096,D=64 fp32, non-causal.
// Reference's exact recurrence (block_max variant), BN=128 fixed, in order.
// All-fp16 tensor path, fp32 accumulate; exp2 domain.
// Two-half QK with packed-P fp16 correction -> 32 fewer live regs;
// __launch_bounds__(128,3) + 48KB smem -> 3 CTAs/SM target.

#define SEQ   4096
#define HD    64
#define BM    64
#define BN    128
#define NTHR  128
#define NBLK  (SEQ / BN)
#define SCL2E 0.18033688011112042f   // (1/8)*log2(e)
#define ONES2 0x3C003C00u            // half2(1,1)

#define NTOT  (2 * 16 * SEQ * HD)

__device__ __half g_q[NTOT];
__device__ __half g_k[NTOT];
__device__ __half g_v[NTOT];

// ---------------- converter ----------------
__global__ __launch_bounds__(512)
void cvt_kernel(const float* __restrict__ q,
                const float* __restrict__ k,
                const float* __restrict__ v)
{
    int i = blockIdx.x * blockDim.x + threadIdx.x;
    if (i >= NTOT / 4) return;

    float4 tq = ((const float4*)q)[i];
    __half2 qa = __floats2half2_rn(tq.x * SCL2E, tq.y * SCL2E);
    __half2 qb = __floats2half2_rn(tq.z * SCL2E, tq.w * SCL2E);
    *(uint2*)(g_q + 4 * i) = make_uint2(*(uint32_t*)&qa, *(uint32_t*)&qb);

    float4 tk = ((const float4*)k)[i];
    __half2 ka = __floats2half2_rn(tk.x, tk.y);
    __half2 kb = __floats2half2_rn(tk.z, tk.w);
    *(uint2*)(g_k + 4 * i) = make_uint2(*(uint32_t*)&ka, *(uint32_t*)&kb);

    float4 tv = ((const float4*)v)[i];
    __half2 va = __floats2half2_rn(tv.x, tv.y);
    __half2 vb = __floats2half2_rn(tv.z, tv.w);
    *(uint2*)(g_v + 4 * i) = make_uint2(*(uint32_t*)&va, *(uint32_t*)&vb);
}

// ---------------- smem layout ----------------
// K slots: 0, 16384 (double-buffered).  V (and transient Q): 32768.
#define O_K0   0
#define O_V    32768
#define SMEM_BYTES 49152      // 48KB -> 3 CTAs/SM (regs permitting)

__device__ __forceinline__ uint32_t swz(uint32_t row, uint32_t ch)
{
    return (row * 8u + (ch ^ (row & 7u))) * 16u;
}

__device__ __forceinline__ void cp16(uint32_t dst, const void* src)
{
    asm volatile("cp.async.cg.shared.global [%0], [%1], 16;" :: "r"(dst), "l"(src));
}
__device__ __forceinline__ void cp_commit() { asm volatile("cp.async.commit_group;"); }
__device__ __forceinline__ void cp_wait0()  { asm volatile("cp.async.wait_group 0;"); }
__device__ __forceinline__ void cp_wait1()  { asm volatile("cp.async.wait_group 1;"); }

__device__ __forceinline__ void ldm_x4(uint32_t a, uint32_t* r)
{
    asm volatile("ldmatrix.sync.aligned.m8n8.x4.shared.b16 {%0,%1,%2,%3}, [%4];"
                 : "=r"(r[0]), "=r"(r[1]), "=r"(r[2]), "=r"(r[3]) : "r"(a));
}
__device__ __forceinline__ void ldm_x4t(uint32_t a, uint32_t* r)
{
    asm volatile("ldmatrix.sync.aligned.m8n8.x4.trans.shared.b16 {%0,%1,%2,%3}, [%4];"
                 : "=r"(r[0]), "=r"(r[1]), "=r"(r[2]), "=r"(r[3]) : "r"(a));
}
__device__ __forceinline__ void mma_fp16(float* c, const uint32_t* a,
                                         const uint32_t* b)
{
    asm volatile(
        "mma.sync.aligned.m16n8k16.row.col.f32.f16.f16.f32 "
        "{%0,%1,%2,%3}, {%4,%5,%6,%7}, {%8,%9}, {%0,%1,%2,%3};"
        : "+f"(c[0]), "+f"(c[1]), "+f"(c[2]), "+f"(c[3])
        : "r"(a[0]), "r"(a[1]), "r"(a[2]), "r"(a[3]), "r"(b[0]), "r"(b[1]));
}
__device__ __forceinline__ uint32_t pack2h(float a, float b)
{
    __half2 t = __floats2half2_rn(a, b);
    return *(uint32_t*)&t;
}
__device__ __forceinline__ float ex2f(float x)
{
    float r; asm("ex2.approx.f32 %0, %1;" : "=f"(r) : "f"(x)); return r;
}
__device__ __forceinline__ uint32_t hmul2u(uint32_t a, uint32_t f)
{
    __half2 r = __hmul2(*(__half2*)&a, *(__half2*)&f);
    return *(uint32_t*)&r;
}

__global__ __launch_bounds__(NTHR, 3)
void fa10_kernel(float* __restrict__ out)
{
    extern __shared__ __align__(16) unsigned char smraw[];
    uint32_t sb = (uint32_t)__cvta_generic_to_shared(smraw);

    const int tid  = threadIdx.x;
    const int lane = tid & 31;
    const int w    = tid >> 5;          // 4 warps, rows w*16..w*16+15
    const int bh   = blockIdx.y;
    const int qb   = blockIdx.x;

    const size_t kvbase = (size_t)bh * SEQ * HD;

    auto tile_ld = [&](uint32_t dstb, const char* srcb) {
        #pragma unroll
        for (int i = 0; i < 8; i++) {
            int c = tid + i * NTHR;
            cp16(dstb + swz(c >> 3, c & 7),
                 srcb + ((size_t)(c >> 3) * HD + (c & 7) * 8) * 2);
        }
    };
    auto load_K = [&](int i) {
        tile_ld(sb + O_K0 + (i & 1) * 16384,
                (const char*)g_k + (kvbase + (size_t)i * BN * HD) * 2);
    };
    auto load_V = [&](int i) {
        tile_ld(sb + O_V,
                (const char*)g_v + (kvbase + (size_t)i * BN * HD) * 2);
    };

    // ---- prologue: Q staged through the V region ----
    {
        const char* qp = (const char*)(g_q + ((size_t)bh * SEQ + (size_t)qb * BM) * HD);
        #pragma unroll
        for (int i = 0; i < 4; i++) {
            int c = tid + i * NTHR;
            cp16(sb + O_V + swz(c >> 3, c & 7),
                 qp + ((size_t)(c >> 3) * HD + (c & 7) * 8) * 2);
        }
    }
    load_K(0);
    cp_commit();                                // g0 = {Q, K0}
    load_K(1);
    cp_commit();                                // g1 = {K1}

    cp_wait1();                                 // g0 done
    __syncthreads();

    uint32_t qf[4][4];
    {
        int quad = lane >> 3, i = lane & 7;
        int row = w * 16 + (quad & 1) * 8 + i;
        #pragma unroll
        for (int t = 0; t < 4; t++)
            ldm_x4(sb + O_V + swz(row, 2 * t + (quad >> 1)), qf[t]);
    }
    __syncthreads();                            // Q reads done
    load_V(0);
    cp_commit();                                // g2 = {V0}

    float o[8][4];
    #pragma unroll
    for (int n = 0; n < 8; n++)
        #pragma unroll
        for (int r = 0; r < 4; r++) o[n][r] = 0.f;
    float osum[4] = {0.f, 0.f, 0.f, 0.f};
    float m0 = -1e30f, m1 = -1e30f;
    const uint32_t bones[2] = {ONES2, ONES2};

    for (int blk = 0; blk < NBLK; blk++) {
        if (blk == 0) cp_wait0(); else cp_wait1();
        __syncthreads();                         // K(blk), V(blk) visible

        uint32_t kh_b = sb + O_K0 + (blk & 1) * 16384;

        const int rowB = (lane & 7) + ((lane >> 4) << 3);
        const int chB  = (lane >> 3) & 1;

        // ---- two-half QK + exp2-pack (c regs reused across halves) ----
        uint32_t pp[32];            // packed fp16 P, pp[16h + 4*tl + k]
        float mxh[2][2];
        #pragma unroll
        for (int h = 0; h < 2; h++) {
            float c[8][4];
            #pragma unroll
            for (int j2 = 0; j2 < 4; j2++) {
                c[2*j2][0] = c[2*j2][1] = c[2*j2][2] = c[2*j2][3] = 0.f;
                c[2*j2+1][0] = c[2*j2+1][1] = c[2*j2+1][2] = c[2*j2+1][3] = 0.f;
                int row = 64 * h + 16 * j2 + rowB;
                #pragma unroll
                for (int t = 0; t < 4; t++) {
                    uint32_t b4[4];
                    ldm_x4(kh_b + swz(row, 2 * t + chB), b4);
                    mma_fp16(c[2*j2],   qf[t], b4);
                    mma_fp16(c[2*j2+1], qf[t], b4 + 2);
                }
            }
            float hx0 = -1e30f, hx1 = -1e30f;
            #pragma unroll
            for (int j = 0; j < 8; j++) {
                hx0 = fmaxf(hx0, fmaxf(c[j][0], c[j][1]));
                hx1 = fmaxf(hx1, fmaxf(c[j][2], c[j][3]));
            }
            hx0 = fmaxf(hx0, __shfl_xor_sync(0xffffffffu, hx0, 1));
            hx0 = fmaxf(hx0, __shfl_xor_sync(0xffffffffu, hx0, 2));
            hx1 = fmaxf(hx1, __shfl_xor_sync(0xffffffffu, hx1, 1));
            hx1 = fmaxf(hx1, __shfl_xor_sync(0xffffffffu, hx1, 2));
            mxh[h][0] = hx0;
            mxh[h][1] = hx1;
            #pragma unroll
            for (int tl = 0; tl < 4; tl++) {
                #pragma unroll
                for (int h2 = 0; h2 < 2; h2++) {
                    int j = 2 * tl + h2;
                    float x0 = ex2f(c[j][0] - hx0);
                    float x1 = ex2f(c[j][1] - hx0);
                    float x2 = ex2f(c[j][2] - hx1);
                    float x3 = ex2f(c[j][3] - hx1);
                    pp[16*h + 4*tl + 2*h2]     = pack2h(x0, x1);
                    pp[16*h + 4*tl + 2*h2 + 1] = pack2h(x2, x3);
                }
            }
        }

        // ---- block max + correction of the lower half ----
        float bm0 = fmaxf(mxh[0][0], mxh[1][0]);
        float bm1 = fmaxf(mxh[0][1], mxh[1][1]);
        #pragma unroll
        for (int h = 0; h < 2; h++) {
            if (__ballot_sync(0xffffffffu,
                              (mxh[h][0] < bm0) || (mxh[h][1] < bm1))) {
                uint32_t f0 = pack2h(ex2f(mxh[h][0] - bm0), ex2f(mxh[h][0] - bm0));
                uint32_t f1 = pack2h(ex2f(mxh[h][1] - bm1), ex2f(mxh[h][1] - bm1));
                #pragma unroll
                for (int k = 0; k < 8; k++) {
                    pp[16*h + 2*k]     = hmul2u(pp[16*h + 2*k],     f0);
                    pp[16*h + 2*k + 1] = hmul2u(pp[16*h + 2*k + 1], f1);
                }
            }
        }

        // ---- rescale O/rowsum (vote-skip; e==1 exactly when no new max) ----
        if (__ballot_sync(0xffffffffu, (bm0 > m0) || (bm1 > m1))) {
            float nm0 = fmaxf(m0, bm0), nm1 = fmaxf(m1, bm1);
            float e0 = ex2f(m0 - nm0), e1 = ex2f(m1 - nm1);
            m0 = nm0; m1 = nm1;
            #pragma unroll
            for (int n = 0; n < 8; n++) {
                o[n][0] *= e0; o[n][1] *= e0;
                o[n][2] *= e1; o[n][3] *= e1;
            }
            osum[0] *= e0; osum[1] *= e0;
            osum[2] *= e1; osum[3] *= e1;
        }

        // ---- PV + ones-MMA rowsum ----
        const int vri = lane & 15;
        const int vch = lane >> 4;
        #pragma unroll
        for (int t = 0; t < 8; t++) {
            const uint32_t* pah = pp + 4 * t;
            int vrow = 16 * t + vri;
            #pragma unroll
            for (int np = 0; np < 4; np++) {
                uint32_t v4[4];
                ldm_x4t(sb + O_V + swz(vrow, 2 * np + vch), v4);
                mma_fp16(o[2*np],   pah, v4);
                mma_fp16(o[2*np+1], pah, v4 + 2);
            }
            mma_fp16(osum, pah, bones);
        }

        // ---- prefetch: V(blk+1), K(blk+2) ----
        __syncthreads();
        if (blk + 1 < NBLK) load_V(blk + 1);
        cp_commit();
        if (blk + 2 < NBLK) load_K(blk + 2);
        cp_commit();
    }

    // ---- epilogue ----
    float inv0 = 1.f / (osum[0] + 1e-6f);
    float inv1 = 1.f / (osum[2] + 1e-6f);
    int r  = lane >> 2;
    int cb = (lane & 3) * 2;
    float* og0 = out + ((size_t)bh * SEQ + (size_t)qb * BM + w * 16 + r) * HD;
    float* og1 = og0 + 8 * HD;
    #pragma unroll
    for (int n = 0; n < 8; n++) {
        *(float2*)(og0 + n * 8 + cb) = make_float2(o[n][0] * inv0, o[n][1] * inv0);
        *(float2*)(og1 + n * 8 + cb) = make_float2(o[n][2] * inv1, o[n][3] * inv1);
    }
}

extern "C" void kernel_launch(void* const* d_in, const int* in_sizes, int n_in,
                              void* d_out, int out_size)
{
    const float* q = (const float*)d_in[0];
    const float* k = (const float*)d_in[1];
    const float* v = (const float*)d_in[2];
    float* o = (float*)d_out;

    int n_bh = in_sizes[0] / (SEQ * HD);    // 32

    cudaFuncSetAttribute(fa10_kernel, cudaFuncAttributeMaxDynamicSharedMemorySize,
                         SMEM_BYTES);

    cvt_kernel<<<(NTOT / 4 + 511) / 512, 512>>>(q, k, v);
    dim3 grid(SEQ / BM, n_bh);
    fa10_kernel<<<grid, NTHR, SMEM_BYTES>>>(o);
}

// round 12
// speedup vs baseline: 1.1166x; 1.1166x over previous
#include <cuda_runtime.h>
#include <cuda_fp16.h>
#include <cstdint>

// FlashAttention B=2,H=16,S=4096,D=64 fp32, non-causal.
// Reference's exact recurrence (block_max variant), BN=128 fixed, in order.
// All-fp16 tensor path, fp32 accumulate:
//   QK^T: Q fp16 x K fp16; PV: P fp16 x V fp16; rowsum via all-ones MMA.
//   exp via ex2.approx.f16x2 on packed (score - blockmax) pairs.
// Triple-buffered K/V (one __syncthreads per iter), warp-vote rescale skip.
// BM=64 / 128 threads / 96KB smem -> 2 CTAs/SM.

#define SEQ   4096
#define HD    64
#define BM    64
#define BN    128
#define NTHR  128
#define NBLK  (SEQ / BN)
// (1/sqrt(64)) * log2(e): scores in log2 domain, exp := ex2.approx
#define SCL2E 0.18033688011112042f
#define ONES2 0x3C003C00u     // half2(1.0, 1.0)

#define NTOT  (2 * 16 * SEQ * HD)

__device__ __half g_q[NTOT];
__device__ __half g_k[NTOT];
__device__ __half g_v[NTOT];

// ---------------- converter ----------------
__global__ __launch_bounds__(512)
void cvt_kernel(const float* __restrict__ q,
                const float* __restrict__ k,
                const float* __restrict__ v)
{
    int i = blockIdx.x * blockDim.x + threadIdx.x;
    if (i >= NTOT / 4) return;

    float4 tq = ((const float4*)q)[i];
    __half2 qa = __floats2half2_rn(tq.x * SCL2E, tq.y * SCL2E);
    __half2 qb = __floats2half2_rn(tq.z * SCL2E, tq.w * SCL2E);
    *(uint2*)(g_q + 4 * i) = make_uint2(*(uint32_t*)&qa, *(uint32_t*)&qb);

    float4 tk = ((const float4*)k)[i];
    __half2 ka = __floats2half2_rn(tk.x, tk.y);
    __half2 kb = __floats2half2_rn(tk.z, tk.w);
    *(uint2*)(g_k + 4 * i) = make_uint2(*(uint32_t*)&ka, *(uint32_t*)&kb);

    float4 tv = ((const float4*)v)[i];
    __half2 va = __floats2half2_rn(tv.x, tv.y);
    __half2 vb = __floats2half2_rn(tv.z, tv.w);
    *(uint2*)(g_v + 4 * i) = make_uint2(*(uint32_t*)&va, *(uint32_t*)&vb);
}

// ---------------- smem layout (byte offsets) ----------------
// K slots: 0, 16384, 32768.  V slots: 49152, 65536, 81920.
#define O_K0   0
#define O_V0   49152
#define SMEM_BYTES 98304      // 96KB -> 2 CTAs/SM

// swizzled byte offset of a 16B chunk (row, chunk in [0,8))
__device__ __forceinline__ uint32_t swz(uint32_t row, uint32_t ch)
{
    return (row * 8u + (ch ^ (row & 7u))) * 16u;
}

__device__ __forceinline__ void cp16(uint32_t dst, const void* src)
{
    asm volatile("cp.async.cg.shared.global [%0], [%1], 16;" :: "r"(dst), "l"(src));
}
__device__ __forceinline__ void cp_commit() { asm volatile("cp.async.commit_group;"); }
__device__ __forceinline__ void cp_wait1()  { asm volatile("cp.async.wait_group 1;"); }

__device__ __forceinline__ void ldm_x4(uint32_t a, uint32_t* r)
{
    asm volatile("ldmatrix.sync.aligned.m8n8.x4.shared.b16 {%0,%1,%2,%3}, [%4];"
                 : "=r"(r[0]), "=r"(r[1]), "=r"(r[2]), "=r"(r[3]) : "r"(a));
}
__device__ __forceinline__ void ldm_x4t(uint32_t a, uint32_t* r)
{
    asm volatile("ldmatrix.sync.aligned.m8n8.x4.trans.shared.b16 {%0,%1,%2,%3}, [%4];"
                 : "=r"(r[0]), "=r"(r[1]), "=r"(r[2]), "=r"(r[3]) : "r"(a));
}
__device__ __forceinline__ void mma_fp16(float* c, const uint32_t* a,
                                         const uint32_t* b)
{
    asm volatile(
        "mma.sync.aligned.m16n8k16.row.col.f32.f16.f16.f32 "
        "{%0,%1,%2,%3}, {%4,%5,%6,%7}, {%8,%9}, {%0,%1,%2,%3};"
        : "+f"(c[0]), "+f"(c[1]), "+f"(c[2]), "+f"(c[3])
        : "r"(a[0]), "r"(a[1]), "r"(a[2]), "r"(a[3]), "r"(b[0]), "r"(b[1]));
}
__device__ __forceinline__ uint32_t pack2h(float a, float b)
{
    __half2 t = __floats2half2_rn(a, b);
    return *(uint32_t*)&t;
}
__device__ __forceinline__ float ex2f(float x)
{
    float r; asm("ex2.approx.f32 %0, %1;" : "=f"(r) : "f"(x)); return r;
}
// packed f16x2 exp2: one MUFU op for two values
__device__ __forceinline__ uint32_t hex2(uint32_t x)
{
    uint32_t r; asm("ex2.approx.f16x2 %0, %1;" : "=r"(r) : "r"(x)); return r;
}

__global__ __launch_bounds__(NTHR, 2)
void fa11_kernel(float* __restrict__ out)
{
    extern __shared__ __align__(16) unsigned char smraw[];
    uint32_t sb = (uint32_t)__cvta_generic_to_shared(smraw);

    const int tid  = threadIdx.x;
    const int lane = tid & 31;
    const int w    = tid >> 5;          // 4 warps, rows w*16..w*16+15
    const int bh   = blockIdx.y;
    const int qb   = blockIdx.x;

    const size_t kvbase = (size_t)bh * SEQ * HD;

    auto tile_ld = [&](uint32_t dstb, const char* srcb) {
        #pragma unroll
        for (int i = 0; i < 8; i++) {           // 1024 chunks (16KB tile)
            int c = tid + i * NTHR;
            cp16(dstb + swz(c >> 3, c & 7),
                 srcb + ((size_t)(c >> 3) * HD + (c & 7) * 8) * 2);
        }
    };
    auto load_K = [&](int i) {
        tile_ld(sb + O_K0 + (i % 3) * 16384,
                (const char*)g_k + (kvbase + (size_t)i * BN * HD) * 2);
    };
    auto load_V = [&](int i) {
        tile_ld(sb + O_V0 + (i % 3) * 16384,
                (const char*)g_v + (kvbase + (size_t)i * BN * HD) * 2);
    };

    // ---- prologue: Q staged through V slot 2 ----
    {
        const char* qp = (const char*)(g_q + ((size_t)bh * SEQ + (size_t)qb * BM) * HD);
        #pragma unroll
        for (int i = 0; i < 4; i++) {           // 512 chunks (Q tile 8KB)
            int c = tid + i * NTHR;
            cp16(sb + O_V0 + 2 * 16384 + swz(c >> 3, c & 7),
                 qp + ((size_t)(c >> 3) * HD + (c & 7) * 8) * 2);
        }
    }
    load_K(0); load_V(0);
    cp_commit();                                // g0 = {Q, K0, V0}
    load_K(1); load_V(1);
    cp_commit();                                // g1 = {K1, V1}

    cp_wait1();                                 // g0 done
    __syncthreads();

    // ---- persistent Q fragments (from V slot 2) ----
    uint32_t qf[4][4];
    {
        int quad = lane >> 3, i = lane & 7;
        int row = w * 16 + (quad & 1) * 8 + i;
        #pragma unroll
        for (int t = 0; t < 4; t++)
            ldm_x4(sb + O_V0 + 2 * 16384 + swz(row, 2 * t + (quad >> 1)), qf[t]);
    }

    float o[8][4];
    #pragma unroll
    for (int n = 0; n < 8; n++)
        #pragma unroll
        for (int r = 0; r < 4; r++) o[n][r] = 0.f;
    float osum[4] = {0.f, 0.f, 0.f, 0.f};       // rowsum via ones-MMA
    float m0 = -1e30f, m1 = -1e30f;
    const uint32_t bones[2] = {ONES2, ONES2};

    for (int blk = 0; blk < NBLK; blk++) {
        if (blk) cp_wait1();                     // K/V(blk) arrived
        __syncthreads();                         // + all warps done with blk-1
        // (sync also orders the Q ldmatrix reads before slot-2 overwrite below)

        uint32_t kh_b = sb + O_K0 + (blk % 3) * 16384;
        uint32_t vh_b = sb + O_V0 + (blk % 3) * 16384;

        // ---- QK^T: Q fp16 x K fp16, 1 MMA per (j2,t,ntile) ----
        float c[16][4];
        const int rowB = (lane & 7) + ((lane >> 4) << 3);
        const int chB  = (lane >> 3) & 1;
        #pragma unroll
        for (int j2 = 0; j2 < 8; j2++) {
            c[2*j2][0] = c[2*j2][1] = c[2*j2][2] = c[2*j2][3] = 0.f;
            c[2*j2+1][0] = c[2*j2+1][1] = c[2*j2+1][2] = c[2*j2+1][3] = 0.f;
            int row = 16 * j2 + rowB;
            #pragma unroll
            for (int t = 0; t < 4; t++) {
                uint32_t b4[4];
                ldm_x4(kh_b + swz(row, 2 * t + chB), b4);
                mma_fp16(c[2*j2],   qf[t], b4);
                mma_fp16(c[2*j2+1], qf[t], b4 + 2);
            }
        }

        // ---- prefetch blk+2 into slot (blk+2)%3 (freed by top sync) ----
        // placed here to spread cp.async smem stores away from the QK
        // ldmatrix burst; still a full iteration of lead time.
        if (blk + 2 < NBLK) { load_K(blk + 2); load_V(blk + 2); }
        cp_commit();                             // one group per iter, always

        // ---- block max (reference recurrence, log2 domain) ----
        float mx0 = -1e30f, mx1 = -1e30f;
        #pragma unroll
        for (int j = 0; j < 16; j++) {
            mx0 = fmaxf(mx0, fmaxf(c[j][0], c[j][1]));
            mx1 = fmaxf(mx1, fmaxf(c[j][2], c[j][3]));
        }
        mx0 = fmaxf(mx0, __shfl_xor_sync(0xffffffffu, mx0, 1));
        mx0 = fmaxf(mx0, __shfl_xor_sync(0xffffffffu, mx0, 2));
        mx1 = fmaxf(mx1, __shfl_xor_sync(0xffffffffu, mx1, 1));
        mx1 = fmaxf(mx1, __shfl_xor_sync(0xffffffffu, mx1, 2));

        // vote-skip rescale: if no row in the warp has a new max, e==2^0==1
        // exactly and the rescale is a no-op (bitwise identical to doing it).
        if (__ballot_sync(0xffffffffu, (mx0 > m0) || (mx1 > m1))) {
            float nm0 = fmaxf(m0, mx0), nm1 = fmaxf(m1, mx1);
            float e0 = ex2f(m0 - nm0), e1 = ex2f(m1 - nm1);
            m0 = nm0; m1 = nm1;
            #pragma unroll
            for (int n = 0; n < 8; n++) {
                o[n][0] *= e0; o[n][1] *= e0;
                o[n][2] *= e1; o[n][3] *= e1;
            }
            osum[0] *= e0; osum[1] *= e0;
            osum[2] *= e1; osum[3] *= e1;
        }

        // ---- chunked pack(c-mx) + f16x2 exp + PV + ones-MMA rowsum ----
        const int vri = lane & 15;
        const int vch = lane >> 4;
        #pragma unroll
        for (int t = 0; t < 8; t++) {
            uint32_t pah[4];
            #pragma unroll
            for (int h = 0; h < 2; h++) {
                int j = 2 * t + h;
                pah[2*h]   = hex2(pack2h(c[j][0] - mx0, c[j][1] - mx0));
                pah[2*h+1] = hex2(pack2h(c[j][2] - mx1, c[j][3] - mx1));
            }
            int vrow = 16 * t + vri;
            #pragma unroll
            for (int np = 0; np < 4; np++) {
                uint32_t v4[4];
                ldm_x4t(vh_b + swz(vrow, 2 * np + vch), v4);
                mma_fp16(o[2*np],   pah, v4);
                mma_fp16(o[2*np+1], pah, v4 + 2);
            }
            mma_fp16(osum, pah, bones);          // rowsum column
        }
    }

    // ---- epilogue: osum[0]=rowsum(r), osum[2]=rowsum(r+8) ----
    float inv0 = 1.f / (osum[0] + 1e-6f);
    float inv1 = 1.f / (osum[2] + 1e-6f);
    int r  = lane >> 2;
    int cb = (lane & 3) * 2;
    float* og0 = out + ((size_t)bh * SEQ + (size_t)qb * BM + w * 16 + r) * HD;
    float* og1 = og0 + 8 * HD;
    #pragma unroll
    for (int n = 0; n < 8; n++) {
        *(float2*)(og0 + n * 8 + cb) = make_float2(o[n][0] * inv0, o[n][1] * inv0);
        *(float2*)(og1 + n * 8 + cb) = make_float2(o[n][2] * inv1, o[n][3] * inv1);
    }
}

extern "C" void kernel_launch(void* const* d_in, const int* in_sizes, int n_in,
                              void* d_out, int out_size)
{
    const float* q = (const float*)d_in[0];
    const float* k = (const float*)d_in[1];
    const float* v = (const float*)d_in[2];
    float* o = (float*)d_out;

    int n_bh = in_sizes[0] / (SEQ * HD);    // 32

    cudaFuncSetAttribute(fa11_kernel, cudaFuncAttributeMaxDynamicSharedMemorySize,
                         SMEM_BYTES);

    cvt_kernel<<<(NTOT / 4 + 511) / 512, 512>>>(q, k, v);
    dim3 grid(SEQ / BM, n_bh);
    fa11_kernel<<<grid, NTHR, SMEM_BYTES>>>(o);
}